// round 3
// baseline (speedup 1.0000x reference)
#include <cuda_runtime.h>
#include <cstdint>

#define L_   197
#define LP_  200       // padded row stride for attn (16B-aligned rows)
#define NB_  128
#define E_   768
#define H_   12
#define HD_  64
#define B_   1536      // NB_*H_
#define NS_  60
#define LT_  257       // L_ + NS_
#define M1_  25216     // L_*NB_
#define M2_  32896     // LT_*NB_
#define OUT_ELEMS 25264128   // M2_*E_
#define AW_ELEMS  6480512    // NB_*LT_*L_

// ---------------- scratch (device globals; allocation-free) ----------------
__device__ float g_q[19365888];   // (B, L, HD)
__device__ float g_k[19365888];
__device__ float g_v[19365888];
__device__ float g_attn[78950400]; // (B, LT, LP_)
__device__ float g_x[25264128];    // (LT*NB, E) gathered AV output

// ---------------- threefry2x32 (bit-exact JAX) ----------------
__device__ __forceinline__ uint32_t rotl32(uint32_t x, int r){ return (x<<r)|(x>>(32-r)); }

__device__ __forceinline__ void tf2x32(uint32_t k0, uint32_t k1, uint32_t x0, uint32_t x1,
                                       uint32_t &o0, uint32_t &o1)
{
    uint32_t ks2 = k0 ^ k1 ^ 0x1BD11BDAu;
#define TFR(r) { x0 += x1; x1 = rotl32(x1, (r)); x1 ^= x0; }
    x0 += k0; x1 += k1;
    TFR(13) TFR(15) TFR(26) TFR(6)
    x0 += k1;  x1 += ks2 + 1u;
    TFR(17) TFR(29) TFR(16) TFR(24)
    x0 += ks2; x1 += k0 + 2u;
    TFR(13) TFR(15) TFR(26) TFR(6)
    x0 += k0;  x1 += k1 + 3u;
    TFR(17) TFR(29) TFR(16) TFR(24)
    x0 += k1;  x1 += ks2 + 4u;
    TFR(13) TFR(15) TFR(26) TFR(6)
    x0 += ks2; x1 += k0 + 5u;
#undef TFR
    o0 = x0; o1 = x1;
}

// partitionable random_bits: element i -> tf(key, hi=0, lo=i), fold y0^y1
__device__ __forceinline__ uint32_t rbits32(uint32_t ka, uint32_t kb, uint32_t i){
    uint32_t o0, o1;
    tf2x32(ka, kb, 0u, i, o0, o1);
    return o0 ^ o1;
}

__device__ __forceinline__ float u01(uint32_t bits){
    return __uint_as_float((bits >> 9) | 0x3f800000u) - 1.0f;
}

// ---------------- block reductions (256 threads, 8 warps) ----------------
__device__ __forceinline__ float blockSum256(float v, float* red){
    #pragma unroll
    for (int o=16;o>0;o>>=1) v += __shfl_xor_sync(0xffffffffu, v, o);
    __syncthreads();
    if ((threadIdx.x & 31) == 0) red[threadIdx.x >> 5] = v;
    __syncthreads();
    float s = red[0];
    #pragma unroll
    for (int i=1;i<8;i++) s += red[i];
    return s;
}

__device__ __forceinline__ float blockMax256(float v, float* red){
    #pragma unroll
    for (int o=16;o>0;o>>=1) v = fmaxf(v, __shfl_xor_sync(0xffffffffu, v, o));
    __syncthreads();
    if ((threadIdx.x & 31) == 0) red[threadIdx.x >> 5] = v;
    __syncthreads();
    float s = red[0];
    #pragma unroll
    for (int i=1;i<8;i++) s = fmaxf(s, red[i]);
    return s;
}

// ---------------- 1. QKV projection SGEMM 128x128x8 + scatter ----------------
__global__ __launch_bounds__(256) void proj_kernel(
    const float* __restrict__ Aq, const float* __restrict__ Ak, const float* __restrict__ Av,
    const float* __restrict__ W, const float* __restrict__ bias)
{
    int p = blockIdx.z;
    const float* A   = (p==0) ? Aq : ((p==1) ? Ak : Av);
    const float* Wp  = W    + (size_t)p*E_*E_;
    const float* bp  = bias + (size_t)p*E_;
    float* outp      = (p==0) ? g_q : ((p==1) ? g_k : g_v);

    __shared__ float As[8][128];
    __shared__ float Bs[8][128];

    int tid  = threadIdx.x;
    int tx   = tid & 15, ty = tid >> 4;
    int lrow = tid >> 1;
    int lk   = (tid & 1) * 4;
    int mBase = blockIdx.y * 128;
    int nBase = blockIdx.x * 128;

    const float* Aptr = A  + (size_t)(mBase + lrow)*E_ + lk;
    const float* Bptr = Wp + (size_t)(nBase + lrow)*E_ + lk;

    float acc[8][8];
    #pragma unroll
    for (int i=0;i<8;i++)
        #pragma unroll
        for (int j=0;j<8;j++) acc[i][j] = 0.f;

    for (int k0 = 0; k0 < E_; k0 += 8) {
        float4 a4 = *(const float4*)(Aptr + k0);
        float4 b4 = *(const float4*)(Bptr + k0);
        __syncthreads();
        As[lk+0][lrow]=a4.x; As[lk+1][lrow]=a4.y; As[lk+2][lrow]=a4.z; As[lk+3][lrow]=a4.w;
        Bs[lk+0][lrow]=b4.x; Bs[lk+1][lrow]=b4.y; Bs[lk+2][lrow]=b4.z; Bs[lk+3][lrow]=b4.w;
        __syncthreads();
        #pragma unroll
        for (int kk=0; kk<8; kk++){
            float av[8], bv[8];
            *(float4*)&av[0] = *(float4*)&As[kk][ty*8];
            *(float4*)&av[4] = *(float4*)&As[kk][ty*8+4];
            *(float4*)&bv[0] = *(float4*)&Bs[kk][tx*8];
            *(float4*)&bv[4] = *(float4*)&Bs[kk][tx*8+4];
            #pragma unroll
            for (int i=0;i<8;i++)
                #pragma unroll
                for (int j=0;j<8;j++) acc[i][j] += av[i]*bv[j];
        }
    }

    float scale = (p==0) ? 0.125f : 1.0f;
    int l = blockIdx.y;
    float bb[8];
    #pragma unroll
    for (int j=0;j<8;j++) bb[j] = bp[nBase + tx*8 + j];

    #pragma unroll
    for (int i=0;i<8;i++){
        int nb = ty*8 + i;                // batch index n within 0..127
        #pragma unroll
        for (int jg=0;jg<8;jg+=4){
            int c = nBase + tx*8 + jg;
            int h = c >> 6, d = c & 63;
            float4 o;
            o.x = (acc[i][jg+0] + bb[jg+0]) * scale;
            o.y = (acc[i][jg+1] + bb[jg+1]) * scale;
            o.z = (acc[i][jg+2] + bb[jg+2]) * scale;
            o.w = (acc[i][jg+3] + bb[jg+3]) * scale;
            *(float4*)&outp[(((size_t)(nb*H_ + h))*L_ + l)*HD_ + d] = o;
        }
    }
}

// ---------------- 2. QK^T, rows scattered into concat slots ----------------
__global__ __launch_bounds__(256) void qk_kernel()
{
    int b  = blockIdx.x;
    int tt = blockIdx.y & 3;
    int ts = blockIdx.y >> 2;
    __shared__ float Qs[64][65];
    __shared__ float Ks[64][65];
    int tid = threadIdx.x;
    int tx = tid & 15, ty = tid >> 4;
    int r0 = tid >> 4;
    int d0 = (tid & 15) * 4;
    const float* qb = g_q + (size_t)b*L_*HD_;
    const float* kb = g_k + (size_t)b*L_*HD_;

    #pragma unroll
    for (int it=0; it<4; it++){
        int r = r0 + it*16;
        int tg = tt*64 + r;
        float4 v = make_float4(0.f,0.f,0.f,0.f);
        if (tg < L_) v = *(const float4*)&qb[(size_t)tg*HD_ + d0];
        Qs[r][d0]=v.x; Qs[r][d0+1]=v.y; Qs[r][d0+2]=v.z; Qs[r][d0+3]=v.w;
        int sg = ts*64 + r;
        float4 w = make_float4(0.f,0.f,0.f,0.f);
        if (sg < L_) w = *(const float4*)&kb[(size_t)sg*HD_ + d0];
        Ks[r][d0]=w.x; Ks[r][d0+1]=w.y; Ks[r][d0+2]=w.z; Ks[r][d0+3]=w.w;
    }
    __syncthreads();

    float acc[4][4];
    #pragma unroll
    for (int i=0;i<4;i++)
        #pragma unroll
        for (int j=0;j<4;j++) acc[i][j]=0.f;

    #pragma unroll 8
    for (int dd=0; dd<64; dd++){
        float a[4], bv[4];
        #pragma unroll
        for (int i=0;i<4;i++) a[i]  = Qs[ty*4+i][dd];
        #pragma unroll
        for (int j=0;j<4;j++) bv[j] = Ks[tx*4+j][dd];
        #pragma unroll
        for (int i=0;i<4;i++)
            #pragma unroll
            for (int j=0;j<4;j++) acc[i][j] += a[i]*bv[j];
    }

    #pragma unroll
    for (int i=0;i<4;i++){
        int t = tt*64 + ty*4 + i;
        if (t >= L_) continue;
        int slot = (t==0) ? 0 : (t + NS_);
        #pragma unroll
        for (int j=0;j<4;j++){
            int s = ts*64 + tx*4 + j;
            if (s < L_) g_attn[((size_t)b*LT_ + slot)*LP_ + s] = acc[i][j];
        }
    }
}

// ---------------- 3. random rows (bit-exact JAX threefry, partitionable) ----------------
__global__ __launch_bounds__(256) void rand_kernel()
{
    int b   = blockIdx.x;
    int tid = threadIdx.x;
    __shared__ float u[L_];
    __shared__ float cosv[NS_], sinv[NS_];
    __shared__ float red[8];
    __shared__ float norm_sh;

    // partitionable split(key(1234)):
    //   k_i = (y0, y1) of tf(key, hi=0, lo=i)
    uint32_t k1a, k1b, k2a, k2b;
    tf2x32(0u, 1234u, 0u, 0u, k1a, k1b);
    tf2x32(0u, 1234u, 0u, 1u, k2a, k2b);

    if (tid < NS_) {
        float f = u01(rbits32(k2a, k2b, (uint32_t)tid));
        float c = f * (0.9f - 0.7f) + 0.7f;
        cosv[tid] = c;
        sinv[tid] = sqrtf(1.0f - c*c);
    }

    float c = 0.f;
    if (tid < L_) c = g_attn[(size_t)b*LT_*LP_ + tid];  // raw center row
    float ss = blockSum256(c*c, red);
    if (tid == 0) norm_sh = sqrtf(ss);
    __syncthreads();
    float norm = norm_sh;
    float nden = fmaxf(norm, 1e-12f);
    if (tid < L_) u[tid] = c / nden;
    __syncthreads();

    for (int n=0; n<NS_; n++){
        float r = 0.f;
        if (tid < L_){
            uint32_t idx = ((uint32_t)n*1536u + (uint32_t)b)*197u + (uint32_t)tid;
            float f = u01(rbits32(k1a, k1b, idx));
            r = f * 2.0f - 1.0f;
        }
        float a = blockSum256((tid < L_) ? r*u[tid] : 0.f, red);
        float t = 0.f;
        if (tid < L_) t = r - a*u[tid];
        float ts = blockSum256(t*t, red);
        float inv = 1.0f / fmaxf(sqrtf(ts), 1e-12f);
        if (tid < L_){
            float w = cosv[n]*u[tid] + sinv[n]*(t*inv);
            g_attn[((size_t)b*LT_ + 1 + n)*LP_ + tid] = w * norm;
        }
    }
}

// ---------------- 4. softmax over last axis (zeroes pad lanes) ----------------
__global__ __launch_bounds__(256) void softmax_kernel()
{
    size_t row = blockIdx.x;
    float* p = g_attn + row*LP_;
    int tid = threadIdx.x;
    __shared__ float red[8];
    float v = (tid < L_) ? p[tid] : -3.402823466e38f;
    float m = blockMax256(v, red);
    float e = (tid < L_) ? expf(v - m) : 0.f;
    float s = blockSum256(e, red);
    if (tid < L_) p[tid] = e / s;
    else if (tid < LP_) p[tid] = 0.f;
}

// ---------------- 5. AV: (LT x L) @ (L x HD), write gathered X layout ----------------
__global__ __launch_bounds__(256) void av_kernel()
{
    int b  = blockIdx.x;
    int tT = blockIdx.y;          // t tile: 0..4
    __shared__ float As[64][65];  // [t][s]
    __shared__ float Vs[64][65];  // [s][d]
    int tid = threadIdx.x;
    int tx = tid & 15, ty = tid >> 4;
    int r0 = tid >> 4;
    int q0 = (tid & 15) * 4;
    const float* attn_b = g_attn + (size_t)b*LT_*LP_;
    const float* vb     = g_v    + (size_t)b*L_*HD_;

    float acc[4][4];
    #pragma unroll
    for (int i=0;i<4;i++)
        #pragma unroll
        for (int j=0;j<4;j++) acc[i][j]=0.f;

    for (int s0=0; s0<L_; s0+=64){
        __syncthreads();
        #pragma unroll
        for (int it=0; it<4; it++){
            int r = r0 + it*16;
            // attn tile (row stride LP_=200, 16B-aligned; pad lanes are zero)
            float4 av = make_float4(0.f,0.f,0.f,0.f);
            int t = tT*64 + r;
            int s = s0 + q0;
            if (t < LT_ && s + 3 < LP_)
                av = *(const float4*)&attn_b[(size_t)t*LP_ + s];
            As[r][q0]=av.x; As[r][q0+1]=av.y; As[r][q0+2]=av.z; As[r][q0+3]=av.w;
            // v tile
            float4 vv = make_float4(0.f,0.f,0.f,0.f);
            int sv = s0 + r;
            if (sv < L_) vv = *(const float4*)&vb[(size_t)sv*HD_ + q0];
            Vs[r][q0]=vv.x; Vs[r][q0+1]=vv.y; Vs[r][q0+2]=vv.z; Vs[r][q0+3]=vv.w;
        }
        __syncthreads();
        #pragma unroll 8
        for (int ssi=0; ssi<64; ssi++){
            float a[4], bv[4];
            #pragma unroll
            for (int i=0;i<4;i++) a[i]  = As[ty*4+i][ssi];
            #pragma unroll
            for (int j=0;j<4;j++) bv[j] = Vs[ssi][tx*4+j];
            #pragma unroll
            for (int i=0;i<4;i++)
                #pragma unroll
                for (int j=0;j<4;j++) acc[i][j] += a[i]*bv[j];
        }
    }

    int n = b / H_, h = b % H_;
    #pragma unroll
    for (int i=0;i<4;i++){
        int t = tT*64 + ty*4 + i;
        if (t >= LT_) continue;
        float4 o = make_float4(acc[i][0], acc[i][1], acc[i][2], acc[i][3]);
        *(float4*)&g_x[((size_t)t*NB_ + n)*E_ + h*HD_ + tx*4] = o;
    }
}

// ---------------- 6. out projection SGEMM 128x128x8 ----------------
__global__ __launch_bounds__(256) void out_gemm(
    const float* __restrict__ W, const float* __restrict__ bias, float* __restrict__ outp)
{
    __shared__ float As[8][128];
    __shared__ float Bs[8][128];
    int tid  = threadIdx.x;
    int tx   = tid & 15, ty = tid >> 4;
    int lrow = tid >> 1;
    int lk   = (tid & 1) * 4;
    int mBase = blockIdx.y * 128;
    int nBase = blockIdx.x * 128;

    const float* Aptr = g_x + (size_t)(mBase + lrow)*E_ + lk;
    const float* Bptr = W   + (size_t)(nBase + lrow)*E_ + lk;

    float acc[8][8];
    #pragma unroll
    for (int i=0;i<8;i++)
        #pragma unroll
        for (int j=0;j<8;j++) acc[i][j]=0.f;

    for (int k0=0; k0<E_; k0+=8){
        float4 a4 = *(const float4*)(Aptr + k0);
        float4 b4 = *(const float4*)(Bptr + k0);
        __syncthreads();
        As[lk+0][lrow]=a4.x; As[lk+1][lrow]=a4.y; As[lk+2][lrow]=a4.z; As[lk+3][lrow]=a4.w;
        Bs[lk+0][lrow]=b4.x; Bs[lk+1][lrow]=b4.y; Bs[lk+2][lrow]=b4.z; Bs[lk+3][lrow]=b4.w;
        __syncthreads();
        #pragma unroll
        for (int kk=0; kk<8; kk++){
            float av[8], bv[8];
            *(float4*)&av[0] = *(float4*)&As[kk][ty*8];
            *(float4*)&av[4] = *(float4*)&As[kk][ty*8+4];
            *(float4*)&bv[0] = *(float4*)&Bs[kk][tx*8];
            *(float4*)&bv[4] = *(float4*)&Bs[kk][tx*8+4];
            #pragma unroll
            for (int i=0;i<8;i++)
                #pragma unroll
                for (int j=0;j<8;j++) acc[i][j] += av[i]*bv[j];
        }
    }

    float bb[8];
    #pragma unroll
    for (int j=0;j<8;j++) bb[j] = bias[nBase + tx*8 + j];

    #pragma unroll
    for (int i=0;i<8;i++){
        int m = mBase + ty*8 + i;
        #pragma unroll
        for (int jg=0;jg<8;jg+=4){
            float4 o;
            o.x = acc[i][jg+0] + bb[jg+0];
            o.y = acc[i][jg+1] + bb[jg+1];
            o.z = acc[i][jg+2] + bb[jg+2];
            o.w = acc[i][jg+3] + bb[jg+3];
            *(float4*)&outp[(size_t)m*E_ + nBase + tx*8 + jg] = o;
        }
    }
}

// ---------------- 7. attn_weights = mean over heads ----------------
__global__ __launch_bounds__(256) void mean_kernel(float* __restrict__ aw)
{
    int idx = blockIdx.x * 256 + threadIdx.x;
    if (idx >= AW_ELEMS) return;
    int s = idx % L_;
    int t = (idx / L_) % LT_;
    int n = idx / (L_ * LT_);
    float sum = 0.f;
    #pragma unroll
    for (int h=0; h<H_; h++)
        sum += g_attn[(((size_t)(n*H_ + h))*LT_ + t)*LP_ + s];
    aw[idx] = sum * (1.0f/12.0f);
}

// ---------------- launch ----------------
extern "C" void kernel_launch(void* const* d_in, const int* in_sizes, int n_in,
                              void* d_out, int out_size)
{
    const float* q   = (const float*)d_in[0];
    const float* k   = (const float*)d_in[1];
    const float* v   = (const float*)d_in[2];
    const float* ipw = (const float*)d_in[3];
    const float* ipb = (const float*)d_in[4];
    const float* opw = (const float*)d_in[5];
    const float* opb = (const float*)d_in[6];
    float* out = (float*)d_out;

    proj_kernel<<<dim3(6,197,3), 256>>>(q, k, v, ipw, ipb);
    qk_kernel<<<dim3(1536,16), 256>>>();
    rand_kernel<<<1536, 256>>>();
    softmax_kernel<<<B_*LT_, 256>>>();
    av_kernel<<<dim3(1536,5), 256>>>();
    out_gemm<<<dim3(6,257), 256>>>(opw, opb, out);
    mean_kernel<<<(AW_ELEMS + 255)/256, 256>>>(out + OUT_ELEMS);
}

// round 5
// speedup vs baseline: 1.9271x; 1.9271x over previous
#include <cuda_runtime.h>
#include <cuda_bf16.h>
#include <cstdint>

#define L_   197
#define LP_  200       // padded row stride for attn (16B-aligned rows)
#define NB_  128
#define E_   768
#define H_   12
#define HD_  64
#define B_   1536      // NB_*H_
#define NS_  60
#define LT_  257       // L_ + NS_
#define OUT_ELEMS 25264128   // M2_*E_
#define AW_ELEMS  6480512    // NB_*LT_*L_

#define STRH 40        // smem row stride in halfs (80 bytes)

// ---------------- scratch (device globals; allocation-free) ----------------
__device__ float g_q[19365888];   // (B, L, HD)
__device__ float g_k[19365888];
__device__ float g_v[19365888];
__device__ float g_attn[78950400]; // (B, LT, LP_)
__device__ float g_x[25264128];    // (LT*NB, E) gathered AV output

// ================= warp-MMA helpers (baseline HMMA, no 'a' features) =======
__device__ __forceinline__ uint32_t smem_u32(const void* p){
    return (uint32_t)__cvta_generic_to_shared(p);
}

__device__ __forceinline__ void ldsm_x4(uint32_t* r, uint32_t addr){
    asm volatile("ldmatrix.sync.aligned.m8n8.x4.shared.b16 {%0,%1,%2,%3}, [%4];"
        : "=r"(r[0]),"=r"(r[1]),"=r"(r[2]),"=r"(r[3]) : "r"(addr));
}

__device__ __forceinline__ void mma_bf16(float* d, const uint32_t* a, const uint32_t* b){
    asm volatile("mma.sync.aligned.m16n8k16.row.col.f32.bf16.bf16.f32 "
        "{%0,%1,%2,%3}, {%4,%5,%6,%7}, {%8,%9}, {%0,%1,%2,%3};"
        : "+f"(d[0]),"+f"(d[1]),"+f"(d[2]),"+f"(d[3])
        : "r"(a[0]),"r"(a[1]),"r"(a[2]),"r"(a[3]), "r"(b[0]),"r"(b[1]));
}

// split fp32 float4 (4 consecutive K elems) into hi/lo bf16, store to smem
__device__ __forceinline__ void cvt_store(__nv_bfloat16* smh, __nv_bfloat16* sml,
                                          int row, int colf, float4 f){
    int off = row*STRH + colf;     // half index
    __nv_bfloat162 h01 = __floats2bfloat162_rn(f.x, f.y);
    __nv_bfloat162 h23 = __floats2bfloat162_rn(f.z, f.w);
    float lx = f.x - __bfloat162float(h01.x);
    float ly = f.y - __bfloat162float(h01.y);
    float lz = f.z - __bfloat162float(h23.x);
    float lw = f.w - __bfloat162float(h23.y);
    __nv_bfloat162 l01 = __floats2bfloat162_rn(lx, ly);
    __nv_bfloat162 l23 = __floats2bfloat162_rn(lz, lw);
    *(uint2*)(smh + off) = make_uint2(*(uint32_t*)&h01, *(uint32_t*)&h23);
    *(uint2*)(sml + off) = make_uint2(*(uint32_t*)&l01, *(uint32_t*)&l23);
}

// C(128x128) = A(128x768) * B(128x768)^T ; acc[2][8][4] per warp (32x64 tile)
__device__ __forceinline__ void gemm_body(const float* __restrict__ Ag,
                                          const float* __restrict__ Bg,
                                          __nv_bfloat16* sAh, __nv_bfloat16* sAl,
                                          __nv_bfloat16* sBh, __nv_bfloat16* sBl,
                                          float acc[2][8][4], int tid)
{
    int lane = tid & 31, wid = tid >> 5;
    int wm = (wid & 3) * 32, wn = (wid >> 2) * 64;

    // ldmatrix per-thread base addresses
    uint32_t aAh = smem_u32(sAh) + (uint32_t)((wm + (lane & 15))*80 + (lane >> 4)*16);
    uint32_t aAl = smem_u32(sAl) + (uint32_t)((wm + (lane & 15))*80 + (lane >> 4)*16);
    int rowB = wn + (lane & 7) + ((lane >> 4) & 1)*8;
    uint32_t aBh = smem_u32(sBh) + (uint32_t)(rowB*80 + ((lane >> 3) & 1)*16);
    uint32_t aBl = smem_u32(sBl) + (uint32_t)(rowB*80 + ((lane >> 3) & 1)*16);

    // gmem load indices: 4 float4 per matrix per chunk
    int r0 = (tid >> 1);                 // not used; compute per-iter below

    for (int ch = 0; ch < 24; ch++){
        int kBase = ch * 32;
        float4 av[4], bv[4];
        int rr[4], cc[4];
        #pragma unroll
        for (int i = 0; i < 4; i++){
            int f = i*256 + tid;
            rr[i] = f >> 3;
            cc[i] = (f & 7) * 4;
            av[i] = *(const float4*)(Ag + (size_t)rr[i]*E_ + kBase + cc[i]);
            bv[i] = *(const float4*)(Bg + (size_t)rr[i]*E_ + kBase + cc[i]);
        }
        __syncthreads();   // previous chunk fully consumed
        #pragma unroll
        for (int i = 0; i < 4; i++){
            cvt_store(sAh, sAl, rr[i], cc[i], av[i]);
            cvt_store(sBh, sBl, rr[i], cc[i], bv[i]);
        }
        __syncthreads();

        #pragma unroll
        for (int ks = 0; ks < 2; ks++){
            uint32_t ah0[4], ah1[4], al0[4], al1[4];
            ldsm_x4(ah0, aAh + ks*32);
            ldsm_x4(ah1, aAh + ks*32 + 16*80);
            ldsm_x4(al0, aAl + ks*32);
            ldsm_x4(al1, aAl + ks*32 + 16*80);
            #pragma unroll
            for (int q = 0; q < 4; q++){
                uint32_t bh[4], bl[4];
                ldsm_x4(bh, aBh + ks*32 + q*16*80);
                ldsm_x4(bl, aBl + ks*32 + q*16*80);
                // n-tiles 2q (bh[0..1]) and 2q+1 (bh[2..3])
                mma_bf16(acc[0][2*q],   ah0, bh);
                mma_bf16(acc[0][2*q],   ah0, bl);
                mma_bf16(acc[0][2*q],   al0, bh);
                mma_bf16(acc[0][2*q+1], ah0, bh+2);
                mma_bf16(acc[0][2*q+1], ah0, bl+2);
                mma_bf16(acc[0][2*q+1], al0, bh+2);
                mma_bf16(acc[1][2*q],   ah1, bh);
                mma_bf16(acc[1][2*q],   ah1, bl);
                mma_bf16(acc[1][2*q],   al1, bh);
                mma_bf16(acc[1][2*q+1], ah1, bh+2);
                mma_bf16(acc[1][2*q+1], ah1, bl+2);
                mma_bf16(acc[1][2*q+1], al1, bh+2);
            }
        }
    }
}

// ---------------- 1. QKV projection (HMMA split-bf16) ----------------
__global__ __launch_bounds__(256, 2) void proj_tc(
    const float* __restrict__ Aq, const float* __restrict__ Ak, const float* __restrict__ Av,
    const float* __restrict__ W, const float* __restrict__ bias)
{
    __shared__ __align__(16) __nv_bfloat16 sAh[128*STRH], sAl[128*STRH];
    __shared__ __align__(16) __nv_bfloat16 sBh[128*STRH], sBl[128*STRH];

    int tid = threadIdx.x, lane = tid & 31, wid = tid >> 5;
    int p = blockIdx.z;
    const float* A  = (p==0) ? Aq : ((p==1) ? Ak : Av);
    const float* Wp = W    + (size_t)p*E_*E_;
    const float* bp = bias + (size_t)p*E_;
    float* outp     = (p==0) ? g_q : ((p==1) ? g_k : g_v);
    float scale     = (p==0) ? 0.125f : 1.0f;

    int l = blockIdx.y;
    int nBase = blockIdx.x * 128;
    size_t mBase = (size_t)l * 128;

    float acc[2][8][4];
    #pragma unroll
    for (int i=0;i<2;i++)
        #pragma unroll
        for (int j=0;j<8;j++)
            #pragma unroll
            for (int c=0;c<4;c++) acc[i][j][c] = 0.f;

    gemm_body(A + mBase*E_, Wp + (size_t)nBase*E_, sAh, sAl, sBh, sBl, acc, tid);

    int wm = (wid & 3) * 32, wn = (wid >> 2) * 64;
    #pragma unroll
    for (int mi = 0; mi < 2; mi++){
        int r = wm + mi*16 + (lane >> 2);   // = batch index nb
        #pragma unroll
        for (int ni = 0; ni < 8; ni++){
            int col = wn + ni*8 + (lane & 3)*2;
            int gc  = nBase + col;
            int h = gc >> 6, d = gc & 63;
            float b0 = bp[gc], b1 = bp[gc+1];
            float2 v0 = make_float2((acc[mi][ni][0] + b0)*scale, (acc[mi][ni][1] + b1)*scale);
            float2 v1 = make_float2((acc[mi][ni][2] + b0)*scale, (acc[mi][ni][3] + b1)*scale);
            *(float2*)&outp[(((size_t)(r*H_ + h))*L_ + l)*HD_ + d] = v0;
            *(float2*)&outp[(((size_t)((r+8)*H_ + h))*L_ + l)*HD_ + d] = v1;
        }
    }
}

// ---------------- 6. out projection (HMMA split-bf16) ----------------
__global__ __launch_bounds__(256, 2) void out_tc(
    const float* __restrict__ W, const float* __restrict__ bias, float* __restrict__ outp)
{
    __shared__ __align__(16) __nv_bfloat16 sAh[128*STRH], sAl[128*STRH];
    __shared__ __align__(16) __nv_bfloat16 sBh[128*STRH], sBl[128*STRH];

    int tid = threadIdx.x, lane = tid & 31, wid = tid >> 5;
    size_t mBase = (size_t)blockIdx.y * 128;
    int nBase = blockIdx.x * 128;

    float acc[2][8][4];
    #pragma unroll
    for (int i=0;i<2;i++)
        #pragma unroll
        for (int j=0;j<8;j++)
            #pragma unroll
            for (int c=0;c<4;c++) acc[i][j][c] = 0.f;

    gemm_body(g_x + mBase*E_, W + (size_t)nBase*E_, sAh, sAl, sBh, sBl, acc, tid);

    int wm = (wid & 3) * 32, wn = (wid >> 2) * 64;
    #pragma unroll
    for (int mi = 0; mi < 2; mi++){
        int r = wm + mi*16 + (lane >> 2);
        #pragma unroll
        for (int ni = 0; ni < 8; ni++){
            int col = wn + ni*8 + (lane & 3)*2;
            int gc  = nBase + col;
            float b0 = bias[gc], b1 = bias[gc+1];
            float2 v0 = make_float2(acc[mi][ni][0] + b0, acc[mi][ni][1] + b1);
            float2 v1 = make_float2(acc[mi][ni][2] + b0, acc[mi][ni][3] + b1);
            *(float2*)&outp[(mBase + r)*E_ + gc] = v0;
            *(float2*)&outp[(mBase + r + 8)*E_ + gc] = v1;
        }
    }
}

// ---------------- threefry2x32 (bit-exact JAX, partitionable) ----------------
__device__ __forceinline__ uint32_t rotl32(uint32_t x, int r){ return (x<<r)|(x>>(32-r)); }

__device__ __forceinline__ void tf2x32(uint32_t k0, uint32_t k1, uint32_t x0, uint32_t x1,
                                       uint32_t &o0, uint32_t &o1)
{
    uint32_t ks2 = k0 ^ k1 ^ 0x1BD11BDAu;
#define TFR(r) { x0 += x1; x1 = rotl32(x1, (r)); x1 ^= x0; }
    x0 += k0; x1 += k1;
    TFR(13) TFR(15) TFR(26) TFR(6)
    x0 += k1;  x1 += ks2 + 1u;
    TFR(17) TFR(29) TFR(16) TFR(24)
    x0 += ks2; x1 += k0 + 2u;
    TFR(13) TFR(15) TFR(26) TFR(6)
    x0 += k0;  x1 += k1 + 3u;
    TFR(17) TFR(29) TFR(16) TFR(24)
    x0 += k1;  x1 += ks2 + 4u;
    TFR(13) TFR(15) TFR(26) TFR(6)
    x0 += ks2; x1 += k0 + 5u;
#undef TFR
    o0 = x0; o1 = x1;
}

__device__ __forceinline__ uint32_t rbits32(uint32_t ka, uint32_t kb, uint32_t i){
    uint32_t o0, o1;
    tf2x32(ka, kb, 0u, i, o0, o1);
    return o0 ^ o1;
}

__device__ __forceinline__ float u01(uint32_t bits){
    return __uint_as_float((bits >> 9) | 0x3f800000u) - 1.0f;
}

// ---------------- block reductions (256 threads, 8 warps) ----------------
__device__ __forceinline__ float blockSum256(float v, float* red){
    #pragma unroll
    for (int o=16;o>0;o>>=1) v += __shfl_xor_sync(0xffffffffu, v, o);
    __syncthreads();
    if ((threadIdx.x & 31) == 0) red[threadIdx.x >> 5] = v;
    __syncthreads();
    float s = red[0];
    #pragma unroll
    for (int i=1;i<8;i++) s += red[i];
    return s;
}

// ---------------- 2. QK^T, rows scattered into concat slots ----------------
__global__ __launch_bounds__(256) void qk_kernel()
{
    int b  = blockIdx.x;
    int tt = blockIdx.y & 3;
    int ts = blockIdx.y >> 2;
    __shared__ float Qs[64][65];
    __shared__ float Ks[64][65];
    int tid = threadIdx.x;
    int tx = tid & 15, ty = tid >> 4;
    int r0 = tid >> 4;
    int d0 = (tid & 15) * 4;
    const float* qb = g_q + (size_t)b*L_*HD_;
    const float* kb = g_k + (size_t)b*L_*HD_;

    #pragma unroll
    for (int it=0; it<4; it++){
        int r = r0 + it*16;
        int tg = tt*64 + r;
        float4 v = make_float4(0.f,0.f,0.f,0.f);
        if (tg < L_) v = *(const float4*)&qb[(size_t)tg*HD_ + d0];
        Qs[r][d0]=v.x; Qs[r][d0+1]=v.y; Qs[r][d0+2]=v.z; Qs[r][d0+3]=v.w;
        int sg = ts*64 + r;
        float4 w = make_float4(0.f,0.f,0.f,0.f);
        if (sg < L_) w = *(const float4*)&kb[(size_t)sg*HD_ + d0];
        Ks[r][d0]=w.x; Ks[r][d0+1]=w.y; Ks[r][d0+2]=w.z; Ks[r][d0+3]=w.w;
    }
    __syncthreads();

    float acc[4][4];
    #pragma unroll
    for (int i=0;i<4;i++)
        #pragma unroll
        for (int j=0;j<4;j++) acc[i][j]=0.f;

    #pragma unroll 8
    for (int dd=0; dd<64; dd++){
        float a[4], bv[4];
        #pragma unroll
        for (int i=0;i<4;i++) a[i]  = Qs[ty*4+i][dd];
        #pragma unroll
        for (int j=0;j<4;j++) bv[j] = Ks[tx*4+j][dd];
        #pragma unroll
        for (int i=0;i<4;i++)
            #pragma unroll
            for (int j=0;j<4;j++) acc[i][j] += a[i]*bv[j];
    }

    #pragma unroll
    for (int i=0;i<4;i++){
        int t = tt*64 + ty*4 + i;
        if (t >= L_) continue;
        int slot = (t==0) ? 0 : (t + NS_);
        #pragma unroll
        for (int j=0;j<4;j++){
            int s = ts*64 + tx*4 + j;
            if (s < L_) g_attn[((size_t)b*LT_ + slot)*LP_ + s] = acc[i][j];
        }
    }
}

// ---------------- 3. random rows (bit-exact JAX threefry, partitionable) ----------------
__global__ __launch_bounds__(256) void rand_kernel()
{
    int b   = blockIdx.x;
    int tid = threadIdx.x;
    __shared__ float u[L_];
    __shared__ float cosv[NS_], sinv[NS_];
    __shared__ float red[8];
    __shared__ float norm_sh;

    uint32_t k1a, k1b, k2a, k2b;
    tf2x32(0u, 1234u, 0u, 0u, k1a, k1b);
    tf2x32(0u, 1234u, 0u, 1u, k2a, k2b);

    if (tid < NS_) {
        float f = u01(rbits32(k2a, k2b, (uint32_t)tid));
        float c = f * (0.9f - 0.7f) + 0.7f;
        cosv[tid] = c;
        sinv[tid] = sqrtf(1.0f - c*c);
    }

    float c = 0.f;
    if (tid < L_) c = g_attn[(size_t)b*LT_*LP_ + tid];
    float ss = blockSum256(c*c, red);
    if (tid == 0) norm_sh = sqrtf(ss);
    __syncthreads();
    float norm = norm_sh;
    float nden = fmaxf(norm, 1e-12f);
    if (tid < L_) u[tid] = c / nden;
    __syncthreads();

    for (int n=0; n<NS_; n++){
        float r = 0.f;
        if (tid < L_){
            uint32_t idx = ((uint32_t)n*1536u + (uint32_t)b)*197u + (uint32_t)tid;
            float f = u01(rbits32(k1a, k1b, idx));
            r = f * 2.0f - 1.0f;
        }
        float a = blockSum256((tid < L_) ? r*u[tid] : 0.f, red);
        float t = 0.f;
        if (tid < L_) t = r - a*u[tid];
        float ts = blockSum256(t*t, red);
        float inv = 1.0f / fmaxf(sqrtf(ts), 1e-12f);
        if (tid < L_){
            float w = cosv[n]*u[tid] + sinv[n]*(t*inv);
            g_attn[((size_t)b*LT_ + 1 + n)*LP_ + tid] = w * norm;
        }
    }
}

// ---------------- 4. softmax: warp per row ----------------
__global__ __launch_bounds__(256) void softmax_kernel()
{
    int wid = threadIdx.x >> 5, lid = threadIdx.x & 31;
    size_t row = (size_t)blockIdx.x * 8 + wid;
    float* p = g_attn + row * LP_;

    float v[7];
    float m = -3.402823466e38f;
    #pragma unroll
    for (int i = 0; i < 7; i++){
        int idx = i*32 + lid;
        v[i] = (idx < L_) ? p[idx] : -3.402823466e38f;
        m = fmaxf(m, v[i]);
    }
    #pragma unroll
    for (int o=16;o>0;o>>=1) m = fmaxf(m, __shfl_xor_sync(0xffffffffu, m, o));
    float s = 0.f;
    #pragma unroll
    for (int i = 0; i < 7; i++){
        v[i] = expf(v[i] - m);
        s += v[i];
    }
    #pragma unroll
    for (int o=16;o>0;o>>=1) s += __shfl_xor_sync(0xffffffffu, s, o);
    float inv = 1.0f / s;
    #pragma unroll
    for (int i = 0; i < 7; i++){
        int idx = i*32 + lid;
        if (idx < L_) p[idx] = v[i] * inv;
        else if (idx < LP_) p[idx] = 0.f;
    }
}

// ---------------- 5. AV: (LT x L) @ (L x HD), write gathered X layout ----------------
__global__ __launch_bounds__(256) void av_kernel()
{
    int b  = blockIdx.x;
    int tT = blockIdx.y;
    __shared__ float As[64][65];
    __shared__ float Vs[64][65];
    int tid = threadIdx.x;
    int tx = tid & 15, ty = tid >> 4;
    int r0 = tid >> 4;
    int q0 = (tid & 15) * 4;
    const float* attn_b = g_attn + (size_t)b*LT_*LP_;
    const float* vb     = g_v    + (size_t)b*L_*HD_;

    float acc[4][4];
    #pragma unroll
    for (int i=0;i<4;i++)
        #pragma unroll
        for (int j=0;j<4;j++) acc[i][j]=0.f;

    for (int s0=0; s0<L_; s0+=64){
        __syncthreads();
        #pragma unroll
        for (int it=0; it<4; it++){
            int r = r0 + it*16;
            float4 av = make_float4(0.f,0.f,0.f,0.f);
            int t = tT*64 + r;
            int s = s0 + q0;
            if (t < LT_ && s + 3 < LP_)
                av = *(const float4*)&attn_b[(size_t)t*LP_ + s];
            As[r][q0]=av.x; As[r][q0+1]=av.y; As[r][q0+2]=av.z; As[r][q0+3]=av.w;
            float4 vv = make_float4(0.f,0.f,0.f,0.f);
            int sv = s0 + r;
            if (sv < L_) vv = *(const float4*)&vb[(size_t)sv*HD_ + q0];
            Vs[r][q0]=vv.x; Vs[r][q0+1]=vv.y; Vs[r][q0+2]=vv.z; Vs[r][q0+3]=vv.w;
        }
        __syncthreads();
        #pragma unroll 8
        for (int ssi=0; ssi<64; ssi++){
            float a[4], bv[4];
            #pragma unroll
            for (int i=0;i<4;i++) a[i]  = As[ty*4+i][ssi];
            #pragma unroll
            for (int j=0;j<4;j++) bv[j] = Vs[ssi][tx*4+j];
            #pragma unroll
            for (int i=0;i<4;i++)
                #pragma unroll
                for (int j=0;j<4;j++) acc[i][j] += a[i]*bv[j];
        }
    }

    int n = b / H_, h = b % H_;
    #pragma unroll
    for (int i=0;i<4;i++){
        int t = tT*64 + ty*4 + i;
        if (t >= LT_) continue;
        float4 o = make_float4(acc[i][0], acc[i][1], acc[i][2], acc[i][3]);
        *(float4*)&g_x[((size_t)t*NB_ + n)*E_ + h*HD_ + tx*4] = o;
    }
}

// ---------------- 7. attn_weights = mean over heads ----------------
__global__ __launch_bounds__(256) void mean_kernel(float* __restrict__ aw)
{
    int idx = blockIdx.x * 256 + threadIdx.x;
    if (idx >= AW_ELEMS) return;
    int s = idx % L_;
    int t = (idx / L_) % LT_;
    int n = idx / (L_ * LT_);
    float sum = 0.f;
    #pragma unroll
    for (int h=0; h<H_; h++)
        sum += g_attn[(((size_t)(n*H_ + h))*LT_ + t)*LP_ + s];
    aw[idx] = sum * (1.0f/12.0f);
}

// ---------------- launch ----------------
extern "C" void kernel_launch(void* const* d_in, const int* in_sizes, int n_in,
                              void* d_out, int out_size)
{
    const float* q   = (const float*)d_in[0];
    const float* k   = (const float*)d_in[1];
    const float* v   = (const float*)d_in[2];
    const float* ipw = (const float*)d_in[3];
    const float* ipb = (const float*)d_in[4];
    const float* opw = (const float*)d_in[5];
    const float* opb = (const float*)d_in[6];
    float* out = (float*)d_out;

    proj_tc<<<dim3(6,197,3), 256>>>(q, k, v, ipw, ipb);
    qk_kernel<<<dim3(1536,16), 256>>>();
    rand_kernel<<<1536, 256>>>();
    softmax_kernel<<<(B_*LT_)/8, 256>>>();
    av_kernel<<<dim3(1536,5), 256>>>();
    out_tc<<<dim3(6,257), 256>>>(opw, opb, out);
    mean_kernel<<<(AW_ELEMS + 255)/256, 256>>>(out + OUT_ELEMS);
}

// round 6
// speedup vs baseline: 2.4514x; 1.2721x over previous
#include <cuda_runtime.h>
#include <cuda_bf16.h>
#include <cstdint>

#define L_   197
#define LP_  200       // padded row stride for attn (16B-aligned rows)
#define NB_  128
#define E_   768
#define H_   12
#define HD_  64
#define B_   1536      // NB_*H_
#define NS_  60
#define LT_  257       // L_ + NS_
#define OUT_ELEMS 25264128   // M2_*E_
#define AW_ELEMS  6480512    // NB_*LT_*L_

#define STRH 40        // smem row stride in halfs (80 bytes) for 32-wide K chunks
#define STR2 72        // smem row stride in halfs (144 bytes) for 64-wide K chunks

// ---------------- scratch (device globals; allocation-free) ----------------
__device__ float g_q[19365888];   // (B, L, HD)
__device__ float g_k[19365888];
__device__ float g_v[19365888];
__device__ float g_attn[78950400]; // (B, LT, LP_)
__device__ float g_x[25264128];    // (LT*NB, E) gathered AV output

// ================= warp-MMA helpers (baseline HMMA, no 'a' features) =======
__device__ __forceinline__ uint32_t smem_u32(const void* p){
    return (uint32_t)__cvta_generic_to_shared(p);
}

__device__ __forceinline__ void ldsm_x4(uint32_t* r, uint32_t addr){
    asm volatile("ldmatrix.sync.aligned.m8n8.x4.shared.b16 {%0,%1,%2,%3}, [%4];"
        : "=r"(r[0]),"=r"(r[1]),"=r"(r[2]),"=r"(r[3]) : "r"(addr));
}

__device__ __forceinline__ void mma_bf16(float* d, const uint32_t* a, const uint32_t* b){
    asm volatile("mma.sync.aligned.m16n8k16.row.col.f32.bf16.bf16.f32 "
        "{%0,%1,%2,%3}, {%4,%5,%6,%7}, {%8,%9}, {%0,%1,%2,%3};"
        : "+f"(d[0]),"+f"(d[1]),"+f"(d[2]),"+f"(d[3])
        : "r"(a[0]),"r"(a[1]),"r"(a[2]),"r"(a[3]), "r"(b[0]),"r"(b[1]));
}

// split fp32 float4 (4 consecutive K elems) into hi/lo bf16, store to smem (stride STRH)
__device__ __forceinline__ void cvt_store(__nv_bfloat16* smh, __nv_bfloat16* sml,
                                          int row, int colf, float4 f){
    int off = row*STRH + colf;
    __nv_bfloat162 h01 = __floats2bfloat162_rn(f.x, f.y);
    __nv_bfloat162 h23 = __floats2bfloat162_rn(f.z, f.w);
    float lx = f.x - __bfloat162float(h01.x);
    float ly = f.y - __bfloat162float(h01.y);
    float lz = f.z - __bfloat162float(h23.x);
    float lw = f.w - __bfloat162float(h23.y);
    __nv_bfloat162 l01 = __floats2bfloat162_rn(lx, ly);
    __nv_bfloat162 l23 = __floats2bfloat162_rn(lz, lw);
    *(uint2*)(smh + off) = make_uint2(*(uint32_t*)&h01, *(uint32_t*)&h23);
    *(uint2*)(sml + off) = make_uint2(*(uint32_t*)&l01, *(uint32_t*)&l23);
}

// same but stride STR2 (64-wide K tiles)
__device__ __forceinline__ void cvt_store72(__nv_bfloat16* smh, __nv_bfloat16* sml,
                                            int row, int colf, float4 f){
    int off = row*STR2 + colf;
    __nv_bfloat162 h01 = __floats2bfloat162_rn(f.x, f.y);
    __nv_bfloat162 h23 = __floats2bfloat162_rn(f.z, f.w);
    float lx = f.x - __bfloat162float(h01.x);
    float ly = f.y - __bfloat162float(h01.y);
    float lz = f.z - __bfloat162float(h23.x);
    float lw = f.w - __bfloat162float(h23.y);
    __nv_bfloat162 l01 = __floats2bfloat162_rn(lx, ly);
    __nv_bfloat162 l23 = __floats2bfloat162_rn(lz, lw);
    *(uint2*)(smh + off) = make_uint2(*(uint32_t*)&h01, *(uint32_t*)&h23);
    *(uint2*)(sml + off) = make_uint2(*(uint32_t*)&l01, *(uint32_t*)&l23);
}

// C(128x128) = A(128x768) * B(128x768)^T ; acc[2][8][4] per warp (32x64 tile)
__device__ __forceinline__ void gemm_body(const float* __restrict__ Ag,
                                          const float* __restrict__ Bg,
                                          __nv_bfloat16* sAh, __nv_bfloat16* sAl,
                                          __nv_bfloat16* sBh, __nv_bfloat16* sBl,
                                          float acc[2][8][4], int tid)
{
    int lane = tid & 31, wid = tid >> 5;
    int wm = (wid & 3) * 32, wn = (wid >> 2) * 64;

    uint32_t aAh = smem_u32(sAh) + (uint32_t)((wm + (lane & 15))*80 + (lane >> 4)*16);
    uint32_t aAl = smem_u32(sAl) + (uint32_t)((wm + (lane & 15))*80 + (lane >> 4)*16);
    int rowB = wn + (lane & 7) + ((lane >> 4) & 1)*8;
    uint32_t aBh = smem_u32(sBh) + (uint32_t)(rowB*80 + ((lane >> 3) & 1)*16);
    uint32_t aBl = smem_u32(sBl) + (uint32_t)(rowB*80 + ((lane >> 3) & 1)*16);

    for (int ch = 0; ch < 24; ch++){
        int kBase = ch * 32;
        float4 av[4], bv[4];
        int rr[4], cc[4];
        #pragma unroll
        for (int i = 0; i < 4; i++){
            int f = i*256 + tid;
            rr[i] = f >> 3;
            cc[i] = (f & 7) * 4;
            av[i] = *(const float4*)(Ag + (size_t)rr[i]*E_ + kBase + cc[i]);
            bv[i] = *(const float4*)(Bg + (size_t)rr[i]*E_ + kBase + cc[i]);
        }
        __syncthreads();
        #pragma unroll
        for (int i = 0; i < 4; i++){
            cvt_store(sAh, sAl, rr[i], cc[i], av[i]);
            cvt_store(sBh, sBl, rr[i], cc[i], bv[i]);
        }
        __syncthreads();

        #pragma unroll
        for (int ks = 0; ks < 2; ks++){
            uint32_t ah0[4], ah1[4], al0[4], al1[4];
            ldsm_x4(ah0, aAh + ks*32);
            ldsm_x4(ah1, aAh + ks*32 + 16*80);
            ldsm_x4(al0, aAl + ks*32);
            ldsm_x4(al1, aAl + ks*32 + 16*80);
            #pragma unroll
            for (int q = 0; q < 4; q++){
                uint32_t bh[4], bl[4];
                ldsm_x4(bh, aBh + ks*32 + q*16*80);
                ldsm_x4(bl, aBl + ks*32 + q*16*80);
                mma_bf16(acc[0][2*q],   ah0, bh);
                mma_bf16(acc[0][2*q],   ah0, bl);
                mma_bf16(acc[0][2*q],   al0, bh);
                mma_bf16(acc[0][2*q+1], ah0, bh+2);
                mma_bf16(acc[0][2*q+1], ah0, bl+2);
                mma_bf16(acc[0][2*q+1], al0, bh+2);
                mma_bf16(acc[1][2*q],   ah1, bh);
                mma_bf16(acc[1][2*q],   ah1, bl);
                mma_bf16(acc[1][2*q],   al1, bh);
                mma_bf16(acc[1][2*q+1], ah1, bh+2);
                mma_bf16(acc[1][2*q+1], ah1, bl+2);
                mma_bf16(acc[1][2*q+1], al1, bh+2);
            }
        }
    }
}

// ---------------- 1. QKV projection (HMMA split-bf16) ----------------
__global__ __launch_bounds__(256, 2) void proj_tc(
    const float* __restrict__ Aq, const float* __restrict__ Ak, const float* __restrict__ Av,
    const float* __restrict__ W, const float* __restrict__ bias)
{
    __shared__ __align__(16) __nv_bfloat16 sAh[128*STRH], sAl[128*STRH];
    __shared__ __align__(16) __nv_bfloat16 sBh[128*STRH], sBl[128*STRH];

    int tid = threadIdx.x, lane = tid & 31, wid = tid >> 5;
    int p = blockIdx.z;
    const float* A  = (p==0) ? Aq : ((p==1) ? Ak : Av);
    const float* Wp = W    + (size_t)p*E_*E_;
    const float* bp = bias + (size_t)p*E_;
    float* outp     = (p==0) ? g_q : ((p==1) ? g_k : g_v);
    float scale     = (p==0) ? 0.125f : 1.0f;

    int l = blockIdx.y;
    int nBase = blockIdx.x * 128;
    size_t mBase = (size_t)l * 128;

    float acc[2][8][4];
    #pragma unroll
    for (int i=0;i<2;i++)
        #pragma unroll
        for (int j=0;j<8;j++)
            #pragma unroll
            for (int c=0;c<4;c++) acc[i][j][c] = 0.f;

    gemm_body(A + mBase*E_, Wp + (size_t)nBase*E_, sAh, sAl, sBh, sBl, acc, tid);

    int wm = (wid & 3) * 32, wn = (wid >> 2) * 64;
    #pragma unroll
    for (int mi = 0; mi < 2; mi++){
        int r = wm + mi*16 + (lane >> 2);
        #pragma unroll
        for (int ni = 0; ni < 8; ni++){
            int col = wn + ni*8 + (lane & 3)*2;
            int gc  = nBase + col;
            int h = gc >> 6, d = gc & 63;
            float b0 = bp[gc], b1 = bp[gc+1];
            float2 v0 = make_float2((acc[mi][ni][0] + b0)*scale, (acc[mi][ni][1] + b1)*scale);
            float2 v1 = make_float2((acc[mi][ni][2] + b0)*scale, (acc[mi][ni][3] + b1)*scale);
            *(float2*)&outp[(((size_t)(r*H_ + h))*L_ + l)*HD_ + d] = v0;
            *(float2*)&outp[(((size_t)((r+8)*H_ + h))*L_ + l)*HD_ + d] = v1;
        }
    }
}

// ---------------- 6. out projection (HMMA split-bf16) ----------------
__global__ __launch_bounds__(256, 2) void out_tc(
    const float* __restrict__ W, const float* __restrict__ bias, float* __restrict__ outp)
{
    __shared__ __align__(16) __nv_bfloat16 sAh[128*STRH], sAl[128*STRH];
    __shared__ __align__(16) __nv_bfloat16 sBh[128*STRH], sBl[128*STRH];

    int tid = threadIdx.x, lane = tid & 31, wid = tid >> 5;
    size_t mBase = (size_t)blockIdx.y * 128;
    int nBase = blockIdx.x * 128;

    float acc[2][8][4];
    #pragma unroll
    for (int i=0;i<2;i++)
        #pragma unroll
        for (int j=0;j<8;j++)
            #pragma unroll
            for (int c=0;c<4;c++) acc[i][j][c] = 0.f;

    gemm_body(g_x + mBase*E_, W + (size_t)nBase*E_, sAh, sAl, sBh, sBl, acc, tid);

    int wm = (wid & 3) * 32, wn = (wid >> 2) * 64;
    #pragma unroll
    for (int mi = 0; mi < 2; mi++){
        int r = wm + mi*16 + (lane >> 2);
        #pragma unroll
        for (int ni = 0; ni < 8; ni++){
            int col = wn + ni*8 + (lane & 3)*2;
            int gc  = nBase + col;
            float b0 = bias[gc], b1 = bias[gc+1];
            float2 v0 = make_float2(acc[mi][ni][0] + b0, acc[mi][ni][1] + b1);
            float2 v1 = make_float2(acc[mi][ni][2] + b0, acc[mi][ni][3] + b1);
            *(float2*)&outp[(mBase + r)*E_ + gc] = v0;
            *(float2*)&outp[(mBase + r + 8)*E_ + gc] = v1;
        }
    }
}

// ---------------- 2. QK^T (HMMA split-bf16), rows scattered into concat slots --------
__global__ __launch_bounds__(256) void qk_mma()
{
    __shared__ __align__(16) __nv_bfloat16 Qh[64*STR2], Ql[64*STR2];
    __shared__ __align__(16) __nv_bfloat16 Kh[64*STR2], Kl[64*STR2];

    int b = blockIdx.x, tt = blockIdx.y;
    int tid = threadIdx.x, lane = tid & 31, wid = tid >> 5;
    const float* qb = g_q + (size_t)b*L_*HD_;
    const float* kb = g_k + (size_t)b*L_*HD_;

    // load Q strip (64 x 64), zero-padded
    #pragma unroll
    for (int i = 0; i < 4; i++){
        int idx = i*256 + tid;
        int r = idx >> 4, c = (idx & 15) * 4;
        int tg = tt*64 + r;
        float4 v = make_float4(0.f,0.f,0.f,0.f);
        if (tg < L_) v = *(const float4*)&qb[(size_t)tg*HD_ + c];
        cvt_store72(Qh, Ql, r, c, v);
    }

    int wm = (wid & 3) * 16, wn = (wid >> 2) * 32;
    uint32_t aQh = smem_u32(Qh) + (uint32_t)((wm + (lane & 15))*144 + (lane >> 4)*16);
    uint32_t aQl = smem_u32(Ql) + (uint32_t)((wm + (lane & 15))*144 + (lane >> 4)*16);
    int rowB = wn + (lane & 7) + ((lane >> 4) & 1)*8;
    uint32_t aKh = smem_u32(Kh) + (uint32_t)(rowB*144 + ((lane >> 3) & 1)*16);
    uint32_t aKl = smem_u32(Kl) + (uint32_t)(rowB*144 + ((lane >> 3) & 1)*16);

    for (int ts = 0; ts < 4; ts++){
        __syncthreads();
        #pragma unroll
        for (int i = 0; i < 4; i++){
            int idx = i*256 + tid;
            int r = idx >> 4, c = (idx & 15) * 4;
            int sg = ts*64 + r;
            float4 v = make_float4(0.f,0.f,0.f,0.f);
            if (sg < L_) v = *(const float4*)&kb[(size_t)sg*HD_ + c];
            cvt_store72(Kh, Kl, r, c, v);
        }
        __syncthreads();

        float acc[4][4];
        #pragma unroll
        for (int i=0;i<4;i++)
            #pragma unroll
            for (int j=0;j<4;j++) acc[i][j] = 0.f;

        #pragma unroll
        for (int ks = 0; ks < 4; ks++){
            uint32_t ah[4], al[4];
            ldsm_x4(ah, aQh + ks*32);
            ldsm_x4(al, aQl + ks*32);
            #pragma unroll
            for (int q = 0; q < 2; q++){
                uint32_t bh[4], bl[4];
                ldsm_x4(bh, aKh + ks*32 + q*16*144);
                ldsm_x4(bl, aKl + ks*32 + q*16*144);
                mma_bf16(acc[2*q],   ah, bh);
                mma_bf16(acc[2*q],   ah, bl);
                mma_bf16(acc[2*q],   al, bh);
                mma_bf16(acc[2*q+1], ah, bh+2);
                mma_bf16(acc[2*q+1], ah, bl+2);
                mma_bf16(acc[2*q+1], al, bh+2);
            }
        }

        int t0 = tt*64 + wm + (lane >> 2);
        int t1 = t0 + 8;
        #pragma unroll
        for (int ni = 0; ni < 4; ni++){
            int s = ts*64 + wn + ni*8 + (lane & 3)*2;
            if (s >= L_) continue;
            bool two = (s + 1 < L_);
            if (t0 < L_){
                int slot = (t0==0) ? 0 : (t0 + NS_);
                float* dst = &g_attn[((size_t)b*LT_ + slot)*LP_ + s];
                if (two) *(float2*)dst = make_float2(acc[ni][0], acc[ni][1]);
                else     dst[0] = acc[ni][0];
            }
            if (t1 < L_){
                int slot = (t1==0) ? 0 : (t1 + NS_);
                float* dst = &g_attn[((size_t)b*LT_ + slot)*LP_ + s];
                if (two) *(float2*)dst = make_float2(acc[ni][2], acc[ni][3]);
                else     dst[0] = acc[ni][2];
            }
        }
    }
}

// ---------------- 5. AV (HMMA split-bf16): (LT x L) @ (L x 64) -> g_x layout --------
__global__ __launch_bounds__(256) void av_mma()
{
    __shared__ __align__(16) __nv_bfloat16 Ah[64*STR2], Al[64*STR2];
    __shared__ __align__(16) __nv_bfloat16 Vh[64*STR2], Vl[64*STR2];

    int b = blockIdx.x, tT = blockIdx.y;   // 0..4
    int tid = threadIdx.x, lane = tid & 31, wid = tid >> 5;
    const float* attn_b = g_attn + (size_t)b*LT_*LP_;
    const float* vb     = g_v    + (size_t)b*L_*HD_;

    int wm = (wid & 3) * 16, wn = (wid >> 2) * 32;
    uint32_t aAh = smem_u32(Ah) + (uint32_t)((wm + (lane & 15))*144 + (lane >> 4)*16);
    uint32_t aAl = smem_u32(Al) + (uint32_t)((wm + (lane & 15))*144 + (lane >> 4)*16);
    int rowB = wn + (lane & 7) + ((lane >> 4) & 1)*8;
    uint32_t aVh = smem_u32(Vh) + (uint32_t)(rowB*144 + ((lane >> 3) & 1)*16);
    uint32_t aVl = smem_u32(Vl) + (uint32_t)(rowB*144 + ((lane >> 3) & 1)*16);

    float acc[4][4];
    #pragma unroll
    for (int i=0;i<4;i++)
        #pragma unroll
        for (int j=0;j<4;j++) acc[i][j] = 0.f;

    for (int s0 = 0; s0 < L_; s0 += 64){
        __syncthreads();
        // attn tile: rows t, cols s (pads in g_attn are zeroed by softmax)
        #pragma unroll
        for (int i = 0; i < 4; i++){
            int idx = i*256 + tid;
            int r = idx >> 4, c = (idx & 15) * 4;
            int t = tT*64 + r, s = s0 + c;
            float4 v = make_float4(0.f,0.f,0.f,0.f);
            if (t < LT_ && s + 3 < LP_) v = *(const float4*)&attn_b[(size_t)t*LP_ + s];
            cvt_store72(Ah, Al, r, c, v);
        }
        // V tile transposed into [d][s]
        #pragma unroll
        for (int i = 0; i < 4; i++){
            int idx = i*256 + tid;
            int r = idx >> 4, c = (idx & 15) * 4;   // r = s row, c = d cols
            int sv = s0 + r;
            float4 v = make_float4(0.f,0.f,0.f,0.f);
            if (sv < L_) v = *(const float4*)&vb[(size_t)sv*HD_ + c];
            float vv[4] = {v.x, v.y, v.z, v.w};
            #pragma unroll
            for (int j = 0; j < 4; j++){
                __nv_bfloat16 h = __float2bfloat16(vv[j]);
                float lo = vv[j] - __bfloat162float(h);
                Vh[(c+j)*STR2 + r] = h;
                Vl[(c+j)*STR2 + r] = __float2bfloat16(lo);
            }
        }
        __syncthreads();

        #pragma unroll
        for (int ks = 0; ks < 4; ks++){
            uint32_t ah[4], al[4];
            ldsm_x4(ah, aAh + ks*32);
            ldsm_x4(al, aAl + ks*32);
            #pragma unroll
            for (int q = 0; q < 2; q++){
                uint32_t bh[4], bl[4];
                ldsm_x4(bh, aVh + ks*32 + q*16*144);
                ldsm_x4(bl, aVl + ks*32 + q*16*144);
                mma_bf16(acc[2*q],   ah, bh);
                mma_bf16(acc[2*q],   ah, bl);
                mma_bf16(acc[2*q],   al, bh);
                mma_bf16(acc[2*q+1], ah, bh+2);
                mma_bf16(acc[2*q+1], ah, bl+2);
                mma_bf16(acc[2*q+1], al, bh+2);
            }
        }
    }

    int n = b / H_, h = b % H_;
    int t0 = tT*64 + wm + (lane >> 2);
    int t1 = t0 + 8;
    #pragma unroll
    for (int ni = 0; ni < 4; ni++){
        int d = wn + ni*8 + (lane & 3)*2;
        if (t0 < LT_)
            *(float2*)&g_x[((size_t)t0*NB_ + n)*E_ + h*HD_ + d] =
                make_float2(acc[ni][0], acc[ni][1]);
        if (t1 < LT_)
            *(float2*)&g_x[((size_t)t1*NB_ + n)*E_ + h*HD_ + d] =
                make_float2(acc[ni][2], acc[ni][3]);
    }
}

// ---------------- threefry2x32 (bit-exact JAX, partitionable) ----------------
__device__ __forceinline__ uint32_t rotl32(uint32_t x, int r){ return (x<<r)|(x>>(32-r)); }

__device__ __forceinline__ void tf2x32(uint32_t k0, uint32_t k1, uint32_t x0, uint32_t x1,
                                       uint32_t &o0, uint32_t &o1)
{
    uint32_t ks2 = k0 ^ k1 ^ 0x1BD11BDAu;
#define TFR(r) { x0 += x1; x1 = rotl32(x1, (r)); x1 ^= x0; }
    x0 += k0; x1 += k1;
    TFR(13) TFR(15) TFR(26) TFR(6)
    x0 += k1;  x1 += ks2 + 1u;
    TFR(17) TFR(29) TFR(16) TFR(24)
    x0 += ks2; x1 += k0 + 2u;
    TFR(13) TFR(15) TFR(26) TFR(6)
    x0 += k0;  x1 += k1 + 3u;
    TFR(17) TFR(29) TFR(16) TFR(24)
    x0 += k1;  x1 += ks2 + 4u;
    TFR(13) TFR(15) TFR(26) TFR(6)
    x0 += ks2; x1 += k0 + 5u;
#undef TFR
    o0 = x0; o1 = x1;
}

__device__ __forceinline__ uint32_t rbits32(uint32_t ka, uint32_t kb, uint32_t i){
    uint32_t o0, o1;
    tf2x32(ka, kb, 0u, i, o0, o1);
    return o0 ^ o1;
}

__device__ __forceinline__ float u01(uint32_t bits){
    return __uint_as_float((bits >> 9) | 0x3f800000u) - 1.0f;
}

// ---------------- block reductions (256 threads, 8 warps) ----------------
__device__ __forceinline__ float blockSum256(float v, float* red){
    #pragma unroll
    for (int o=16;o>0;o>>=1) v += __shfl_xor_sync(0xffffffffu, v, o);
    __syncthreads();
    if ((threadIdx.x & 31) == 0) red[threadIdx.x >> 5] = v;
    __syncthreads();
    float s = red[0];
    #pragma unroll
    for (int i=1;i<8;i++) s += red[i];
    return s;
}

// ---------------- 3. random rows (bit-exact JAX threefry, partitionable) ----------------
__global__ __launch_bounds__(256) void rand_kernel()
{
    int b   = blockIdx.x;
    int tid = threadIdx.x;
    __shared__ float u[L_];
    __shared__ float cosv[NS_], sinv[NS_];
    __shared__ float red[8];
    __shared__ float norm_sh;

    uint32_t k1a, k1b, k2a, k2b;
    tf2x32(0u, 1234u, 0u, 0u, k1a, k1b);
    tf2x32(0u, 1234u, 0u, 1u, k2a, k2b);

    if (tid < NS_) {
        float f = u01(rbits32(k2a, k2b, (uint32_t)tid));
        float c = f * (0.9f - 0.7f) + 0.7f;
        cosv[tid] = c;
        sinv[tid] = sqrtf(1.0f - c*c);
    }

    float c = 0.f;
    if (tid < L_) c = g_attn[(size_t)b*LT_*LP_ + tid];
    float ss = blockSum256(c*c, red);
    if (tid == 0) norm_sh = sqrtf(ss);
    __syncthreads();
    float norm = norm_sh;
    float nden = fmaxf(norm, 1e-12f);
    if (tid < L_) u[tid] = c / nden;
    __syncthreads();

    for (int n=0; n<NS_; n++){
        float r = 0.f;
        if (tid < L_){
            uint32_t idx = ((uint32_t)n*1536u + (uint32_t)b)*197u + (uint32_t)tid;
            float f = u01(rbits32(k1a, k1b, idx));
            r = f * 2.0f - 1.0f;
        }
        float a = blockSum256((tid < L_) ? r*u[tid] : 0.f, red);
        float t = 0.f;
        if (tid < L_) t = r - a*u[tid];
        float ts = blockSum256(t*t, red);
        float inv = 1.0f / fmaxf(sqrtf(ts), 1e-12f);
        if (tid < L_){
            float w = cosv[n]*u[tid] + sinv[n]*(t*inv);
            g_attn[((size_t)b*LT_ + 1 + n)*LP_ + tid] = w * norm;
        }
    }
}

// ---------------- 4. softmax: warp per row ----------------
__global__ __launch_bounds__(256) void softmax_kernel()
{
    int wid = threadIdx.x >> 5, lid = threadIdx.x & 31;
    size_t row = (size_t)blockIdx.x * 8 + wid;
    float* p = g_attn + row * LP_;

    float v[7];
    float m = -3.402823466e38f;
    #pragma unroll
    for (int i = 0; i < 7; i++){
        int idx = i*32 + lid;
        v[i] = (idx < L_) ? p[idx] : -3.402823466e38f;
        m = fmaxf(m, v[i]);
    }
    #pragma unroll
    for (int o=16;o>0;o>>=1) m = fmaxf(m, __shfl_xor_sync(0xffffffffu, m, o));
    float s = 0.f;
    #pragma unroll
    for (int i = 0; i < 7; i++){
        v[i] = expf(v[i] - m);
        s += v[i];
    }
    #pragma unroll
    for (int o=16;o>0;o>>=1) s += __shfl_xor_sync(0xffffffffu, s, o);
    float inv = 1.0f / s;
    #pragma unroll
    for (int i = 0; i < 7; i++){
        int idx = i*32 + lid;
        if (idx < L_) p[idx] = v[i] * inv;
        else if (idx < LP_) p[idx] = 0.f;
    }
}

// ---------------- 7. attn_weights = mean over heads ----------------
__global__ __launch_bounds__(256) void mean_kernel(float* __restrict__ aw)
{
    int idx = blockIdx.x * 256 + threadIdx.x;
    if (idx >= AW_ELEMS) return;
    int s = idx % L_;
    int t = (idx / L_) % LT_;
    int n = idx / (L_ * LT_);
    float sum = 0.f;
    #pragma unroll
    for (int h=0; h<H_; h++)
        sum += g_attn[(((size_t)(n*H_ + h))*LT_ + t)*LP_ + s];
    aw[idx] = sum * (1.0f/12.0f);
}

// ---------------- launch ----------------
extern "C" void kernel_launch(void* const* d_in, const int* in_sizes, int n_in,
                              void* d_out, int out_size)
{
    const float* q   = (const float*)d_in[0];
    const float* k   = (const float*)d_in[1];
    const float* v   = (const float*)d_in[2];
    const float* ipw = (const float*)d_in[3];
    const float* ipb = (const float*)d_in[4];
    const float* opw = (const float*)d_in[5];
    const float* opb = (const float*)d_in[6];
    float* out = (float*)d_out;

    proj_tc<<<dim3(6,197,3), 256>>>(q, k, v, ipw, ipb);
    qk_mma<<<dim3(1536,4), 256>>>();
    rand_kernel<<<1536, 256>>>();
    softmax_kernel<<<(B_*LT_)/8, 256>>>();
    av_mma<<<dim3(1536,5), 256>>>();
    out_tc<<<dim3(6,257), 256>>>(opw, opb, out);
    mean_kernel<<<(AW_ELEMS + 255)/256, 256>>>(out + OUT_ELEMS);
}